// round 1
// baseline (speedup 1.0000x reference)
#include <cuda_runtime.h>

// Problem constants (fixed by the dataset):
//   x:     (B, 3)  float32, B = 131072
//   knots: (3, 48) float32
//   grid:  (48, 48, 48, 16) float32
//   out:   (B, 16) float32
#define NK 48          // knots per dim
#define NP 50          // padded grid extent per dim (NK + 2)
#define NV 16          // channels

// Padded grid scratch: 50^3 * 16 floats = 8 MB. __device__ global (no allocation).
__device__ float g_padded[NP * NP * NP * NV];

// ---------------------------------------------------------------------------
// Kernel 1: build padded grid with linear extrapolation along each axis.
// Padding is a separable linear operator, so each padded element is a
// product-combination of at most 2 source indices per axis (<= 8 terms).
// ---------------------------------------------------------------------------
__device__ __forceinline__ int pad_terms(int I, int* s, float* c) {
    if (I == 0)      { s[0] = 0;      c[0] = 2.0f; s[1] = 1;      c[1] = -1.0f; return 2; }
    if (I == NP - 1) { s[0] = NK - 1; c[0] = 2.0f; s[1] = NK - 2; c[1] = -1.0f; return 2; }
    s[0] = I - 1; c[0] = 1.0f; return 1;
}

__global__ void pad_kernel(const float* __restrict__ grid) {
    int idx = blockIdx.x * blockDim.x + threadIdx.x;
    const int TOT = NP * NP * NP;
    if (idx >= TOT) return;
    int K = idx % NP;
    int t = idx / NP;
    int J = t % NP;
    int I = t / NP;

    int si[2], sj[2], sk[2];
    float ci[2], cj[2], ck[2];
    int ni = pad_terms(I, si, ci);
    int nj = pad_terms(J, sj, cj);
    int nk = pad_terms(K, sk, ck);

    float4 acc0 = make_float4(0.f, 0.f, 0.f, 0.f);
    float4 acc1 = acc0, acc2 = acc0, acc3 = acc0;

    for (int a = 0; a < ni; a++)
        for (int b = 0; b < nj; b++)
            for (int c = 0; c < nk; c++) {
                float w = ci[a] * cj[b] * ck[c];
                const float4* src = reinterpret_cast<const float4*>(
                    grid + ((si[a] * NK + sj[b]) * NK + sk[c]) * NV);
                float4 v0 = src[0], v1 = src[1], v2 = src[2], v3 = src[3];
                acc0.x += w * v0.x; acc0.y += w * v0.y; acc0.z += w * v0.z; acc0.w += w * v0.w;
                acc1.x += w * v1.x; acc1.y += w * v1.y; acc1.z += w * v1.z; acc1.w += w * v1.w;
                acc2.x += w * v2.x; acc2.y += w * v2.y; acc2.z += w * v2.z; acc2.w += w * v2.w;
                acc3.x += w * v3.x; acc3.y += w * v3.y; acc3.z += w * v3.z; acc3.w += w * v3.w;
            }

    float4* dst = reinterpret_cast<float4*>(g_padded + idx * NV);
    dst[0] = acc0; dst[1] = acc1; dst[2] = acc2; dst[3] = acc3;
}

// ---------------------------------------------------------------------------
// Kernel 2: per-point Catmull-Rom weights + 4x4x4 gather-contract.
// 4 lanes per point; each lane owns 4 channels (one float4).
// ---------------------------------------------------------------------------
__global__ __launch_bounds__(256)
void interp_kernel(const float* __restrict__ x,
                   const float* __restrict__ knots,
                   float4* __restrict__ out, int B) {
    __shared__ float sk[3 * NK];
    for (int i = threadIdx.x; i < 3 * NK; i += blockDim.x) sk[i] = knots[i];
    __syncthreads();

    int gtid = blockIdx.x * blockDim.x + threadIdx.x;
    int p  = gtid >> 2;   // point index
    int c4 = gtid & 3;    // float4 channel group
    if (p >= B) return;

    float w[3][4];
    int base[3];

    #pragma unroll
    for (int d = 0; d < 3; d++) {
        float xd = x[p * 3 + d];
        const float* kd = sk + d * NK;

        // upper_bound: count of kd[i] <= xd, then -1, clipped to [0, NK-2]
        int lo = 0, hi = NK;
        while (lo < hi) {
            int mid = (lo + hi) >> 1;
            if (kd[mid] <= xd) lo = mid + 1; else hi = mid;
        }
        int idx = lo - 1;
        idx = idx < 0 ? 0 : (idx > NK - 2 ? NK - 2 : idx);

        float t0 = kd[idx], t1 = kd[idx + 1];
        float dt = t1 - t0;
        float u  = (xd - t0) / dt;
        float u2 = u * u;
        float u3 = u2 * u;
        float h00 =  2.0f * u3 - 3.0f * u2 + 1.0f;
        float h10 =         u3 - 2.0f * u2 + u;
        float h01 = -2.0f * u3 + 3.0f * u2;
        float h11 =         u3 -        u2;

        // one-sided tangents via padded knot array tp
        float tpm = (idx == 0)      ? 2.0f * kd[0]      - kd[1]      : kd[idx - 1];
        float tpp = (idx == NK - 2) ? 2.0f * kd[NK - 1] - kd[NK - 2] : kd[idx + 2];
        float a = dt / (t1 - tpm);    // tp[idx+2] - tp[idx]
        float b = dt / (tpp - t0);    // tp[idx+3] - tp[idx+1]

        w[d][0] = -h10 * a;
        w[d][1] =  h00 - h11 * b;
        w[d][2] =  h01 + h10 * a;
        w[d][3] =  h11 * b;
        base[d] = idx;
    }

    const float4* __restrict__ G = reinterpret_cast<const float4*>(g_padded);
    // float4 element index of P[I][J][K] channel-group c4:
    //   ((I*NP + J)*NP + K)*4 + c4
    float4 acc = make_float4(0.f, 0.f, 0.f, 0.f);

    #pragma unroll
    for (int i = 0; i < 4; i++) {
        float wi = w[0][i];
        int ibase = (base[0] + i) * NP;
        #pragma unroll
        for (int j = 0; j < 4; j++) {
            float wij = wi * w[1][j];
            long row = ((long)(ibase + base[1] + j) * NP + base[2]) * 4 + c4;
            float4 v0 = G[row];
            float4 v1 = G[row + 4];
            float4 v2 = G[row + 8];
            float4 v3 = G[row + 12];
            float wk0 = wij * w[2][0];
            float wk1 = wij * w[2][1];
            float wk2 = wij * w[2][2];
            float wk3 = wij * w[2][3];
            acc.x += wk0 * v0.x; acc.y += wk0 * v0.y; acc.z += wk0 * v0.z; acc.w += wk0 * v0.w;
            acc.x += wk1 * v1.x; acc.y += wk1 * v1.y; acc.z += wk1 * v1.z; acc.w += wk1 * v1.w;
            acc.x += wk2 * v2.x; acc.y += wk2 * v2.y; acc.z += wk2 * v2.z; acc.w += wk2 * v2.w;
            acc.x += wk3 * v3.x; acc.y += wk3 * v3.y; acc.z += wk3 * v3.z; acc.w += wk3 * v3.w;
        }
    }

    out[(long)p * 4 + c4] = acc;
}

extern "C" void kernel_launch(void* const* d_in, const int* in_sizes, int n_in,
                              void* d_out, int out_size) {
    const float* x     = (const float*)d_in[0];   // (B, 3)
    const float* knots = (const float*)d_in[1];   // (3, 48)
    const float* grid  = (const float*)d_in[2];   // (48, 48, 48, 16)
    float4* out = (float4*)d_out;                 // (B, 16)

    int B = in_sizes[0] / 3;

    // 1) build padded grid
    const int TOT = NP * NP * NP;
    pad_kernel<<<(TOT + 255) / 256, 256>>>(grid);

    // 2) interpolate: 4 threads per point
    long threads = (long)B * 4;
    int blocks = (int)((threads + 255) / 256);
    interp_kernel<<<blocks, 256>>>(x, knots, out, B);
}

// round 2
// speedup vs baseline: 1.1050x; 1.1050x over previous
#include <cuda_runtime.h>

// Problem constants (fixed by the dataset):
//   x:     (B, 3)  float32, B = 131072
//   knots: (3, 48) float32
//   grid:  (48, 48, 48, 16) float32
//   out:   (B, 16) float32
#define NK 48          // knots per dim
#define NP 50          // padded grid extent per dim (NK + 2)
#define NV 16          // channels

// Padded grid scratch: 50^3 * 16 floats = 8 MB. __device__ global (no allocation).
__device__ float g_padded[NP * NP * NP * NV];

// ---------------------------------------------------------------------------
// Kernel 1: build padded grid with linear extrapolation along each axis.
// ---------------------------------------------------------------------------
__device__ __forceinline__ int pad_terms(int I, int* s, float* c) {
    if (I == 0)      { s[0] = 0;      c[0] = 2.0f; s[1] = 1;      c[1] = -1.0f; return 2; }
    if (I == NP - 1) { s[0] = NK - 1; c[0] = 2.0f; s[1] = NK - 2; c[1] = -1.0f; return 2; }
    s[0] = I - 1; c[0] = 1.0f; return 1;
}

__global__ void pad_kernel(const float* __restrict__ grid) {
    int idx = blockIdx.x * blockDim.x + threadIdx.x;
    const int TOT = NP * NP * NP;
    if (idx >= TOT) return;
    int K = idx % NP;
    int t = idx / NP;
    int J = t % NP;
    int I = t / NP;

    int si[2], sj[2], skk[2];
    float ci[2], cj[2], ck[2];
    int ni = pad_terms(I, si, ci);
    int nj = pad_terms(J, sj, cj);
    int nk = pad_terms(K, skk, ck);

    float4 acc0 = make_float4(0.f, 0.f, 0.f, 0.f);
    float4 acc1 = acc0, acc2 = acc0, acc3 = acc0;

    for (int a = 0; a < ni; a++)
        for (int b = 0; b < nj; b++)
            for (int c = 0; c < nk; c++) {
                float w = ci[a] * cj[b] * ck[c];
                const float4* src = reinterpret_cast<const float4*>(
                    grid + ((si[a] * NK + sj[b]) * NK + skk[c]) * NV);
                float4 v0 = src[0], v1 = src[1], v2 = src[2], v3 = src[3];
                acc0.x += w * v0.x; acc0.y += w * v0.y; acc0.z += w * v0.z; acc0.w += w * v0.w;
                acc1.x += w * v1.x; acc1.y += w * v1.y; acc1.z += w * v1.z; acc1.w += w * v1.w;
                acc2.x += w * v2.x; acc2.y += w * v2.y; acc2.z += w * v2.z; acc2.w += w * v2.w;
                acc3.x += w * v3.x; acc3.y += w * v3.y; acc3.z += w * v3.z; acc3.w += w * v3.w;
            }

    float4* dst = reinterpret_cast<float4*>(g_padded + idx * NV);
    dst[0] = acc0; dst[1] = acc1; dst[2] = acc2; dst[3] = acc3;
}

// ---------------------------------------------------------------------------
// Kernel 2: 16 lanes per point. The 16 lanes of a point jointly load one
// contiguous 256B K-row per (i,j) iteration -> each warp LDG touches 2x256B
// contiguous segments instead of 8x64B scattered ones (halves L1 wavefronts).
// Lane l owns (kk = l>>2, c4 = l&3). Cross-kk reduction via shfl_xor at end.
// ---------------------------------------------------------------------------
__global__ __launch_bounds__(256)
void interp_kernel(const float* __restrict__ x,
                   const float* __restrict__ knots,
                   float4* __restrict__ out, int B) {
    __shared__ float sk[3 * NK];
    for (int i = threadIdx.x; i < 3 * NK; i += blockDim.x) sk[i] = knots[i];
    __syncthreads();

    const int tid = threadIdx.x;
    const int l   = tid & 15;          // lane within 16-lane point group
    const int p   = blockIdx.x * 16 + (tid >> 4);
    // B = 131072, grid = B/16 blocks exactly; no partial groups.

    // ---- cooperative weight computation: lanes 0..2 each do one dim ----
    float4 wv = make_float4(0.f, 0.f, 0.f, 0.f);
    int idxv = 0;
    if (l < 3) {
        const int d = l;
        const float xd = x[p * 3 + d];
        const float* kd = sk + d * NK;

        int lo = 0, hi = NK;                      // upper_bound
        #pragma unroll
        for (int it = 0; it < 6; it++) {          // ceil(log2(48)) = 6
            int mid = (lo + hi) >> 1;
            if (kd[mid] <= xd) lo = mid + 1; else hi = mid;
        }
        int idx = lo - 1;
        idx = idx < 0 ? 0 : (idx > NK - 2 ? NK - 2 : idx);

        float t0 = kd[idx], t1 = kd[idx + 1];
        float dt = t1 - t0;
        float u  = (xd - t0) / dt;
        float u2 = u * u;
        float u3 = u2 * u;
        float h00 =  2.0f * u3 - 3.0f * u2 + 1.0f;
        float h10 =         u3 - 2.0f * u2 + u;
        float h01 = -2.0f * u3 + 3.0f * u2;
        float h11 =         u3 -        u2;

        float tpm = (idx == 0)      ? 2.0f * kd[0]      - kd[1]      : kd[idx - 1];
        float tpp = (idx == NK - 2) ? 2.0f * kd[NK - 1] - kd[NK - 2] : kd[idx + 2];
        float a = dt / (t1 - tpm);
        float b = dt / (tpp - t0);

        wv = make_float4(-h10 * a, h00 - h11 * b, h01 + h10 * a, h11 * b);
        idxv = idx;
    }

    // ---- broadcast weights + bases within the 16-lane group ----
    const unsigned FULL = 0xffffffffu;
    float w0[4], w1[4], w2[4];
    w0[0] = __shfl_sync(FULL, wv.x, 0, 16);
    w0[1] = __shfl_sync(FULL, wv.y, 0, 16);
    w0[2] = __shfl_sync(FULL, wv.z, 0, 16);
    w0[3] = __shfl_sync(FULL, wv.w, 0, 16);
    w1[0] = __shfl_sync(FULL, wv.x, 1, 16);
    w1[1] = __shfl_sync(FULL, wv.y, 1, 16);
    w1[2] = __shfl_sync(FULL, wv.z, 1, 16);
    w1[3] = __shfl_sync(FULL, wv.w, 1, 16);
    w2[0] = __shfl_sync(FULL, wv.x, 2, 16);
    w2[1] = __shfl_sync(FULL, wv.y, 2, 16);
    w2[2] = __shfl_sync(FULL, wv.z, 2, 16);
    w2[3] = __shfl_sync(FULL, wv.w, 2, 16);
    int b0 = __shfl_sync(FULL, idxv, 0, 16);
    int b1 = __shfl_sync(FULL, idxv, 1, 16);
    int b2 = __shfl_sync(FULL, idxv, 2, 16);

    const int kk = l >> 2;
    const float wk = (kk == 0) ? w2[0] : (kk == 1) ? w2[1] : (kk == 2) ? w2[2] : w2[3];

    // ---- gather: 16 fully-unrolled 128-bit loads, each lane one float4/row ----
    const float4* __restrict__ G4 = reinterpret_cast<const float4*>(g_padded);
    // float4 index of (I, J, b2+kk, c4) = ((I*NP + J)*NP + b2)*4 + (kk*4 + c4)
    //                                   = rowstart(I,J) + l
    const int baseoff = ((b0 * NP + b1) * NP + b2) * 4 + l;

    float4 acc = make_float4(0.f, 0.f, 0.f, 0.f);
    #pragma unroll
    for (int i = 0; i < 4; i++) {
        #pragma unroll
        for (int j = 0; j < 4; j++) {
            float wij = w0[i] * w1[j] * wk;
            float4 v = G4[baseoff + i * (NP * NP * 4) + j * (NP * 4)];
            acc.x += wij * v.x;
            acc.y += wij * v.y;
            acc.z += wij * v.z;
            acc.w += wij * v.w;
        }
    }

    // ---- reduce over kk (lanes l, l^4, l^8, l^12 share c4) ----
    acc.x += __shfl_xor_sync(FULL, acc.x, 4);
    acc.y += __shfl_xor_sync(FULL, acc.y, 4);
    acc.z += __shfl_xor_sync(FULL, acc.z, 4);
    acc.w += __shfl_xor_sync(FULL, acc.w, 4);
    acc.x += __shfl_xor_sync(FULL, acc.x, 8);
    acc.y += __shfl_xor_sync(FULL, acc.y, 8);
    acc.z += __shfl_xor_sync(FULL, acc.z, 8);
    acc.w += __shfl_xor_sync(FULL, acc.w, 8);

    if (kk == 0) {
        out[(long)p * 4 + (l & 3)] = acc;
    }
}

extern "C" void kernel_launch(void* const* d_in, const int* in_sizes, int n_in,
                              void* d_out, int out_size) {
    const float* x     = (const float*)d_in[0];   // (B, 3)
    const float* knots = (const float*)d_in[1];   // (3, 48)
    const float* grid  = (const float*)d_in[2];   // (48, 48, 48, 16)
    float4* out = (float4*)d_out;                 // (B, 16)

    int B = in_sizes[0] / 3;

    const int TOT = NP * NP * NP;
    pad_kernel<<<(TOT + 255) / 256, 256>>>(grid);

    // 16 threads per point
    long threads = (long)B * 16;
    int blocks = (int)((threads + 255) / 256);
    interp_kernel<<<blocks, 256>>>(x, knots, out, B);
}